// round 15
// baseline (speedup 1.0000x reference)
#include <cuda_runtime.h>

#define IN_FEATURES 212445
#define N1 65536
#define N2 16384
#define NBINS 128
#define NCLS 20
#define BATCH 32

#define ACC_THREADS 64
#define ACC_CHUNKS 27
#define NGROUPS ((IN_FEATURES + 3) / 4)   // 53112 groups of 4 features

#define CB ((NGROUPS + 255) / 256)        // 208 compose blocks
#define HB 64                             // hist blocks (64 x 256 x 4 = 65536)
#define SETUP_BLOCKS (CB + HB + NCLS)     // 292

#define ACC_BLOCKS (ACC_CHUNKS * BATCH)   // 864

// ---------------- device scratch (no allocation allowed) ----------------
__device__ unsigned int g_m8[NGROUPS];           // composed map, 4 bins packed/uint
__device__ __align__(16) float g_pcc1[NBINS * HB];   // cc1 partials [m][block]
__device__ __align__(16) float g_pcnt2[NBINS * 16];  // cnt2 partials [m][block16]
__device__ float g_Gt[NBINS * NCLS];             // folded FC weights, [m][cls] (plain stores)
__device__ float g_GB[NCLS * NBINS];             // fcw . B  per (cls,m)
__device__ float g_GC[NCLS * NBINS];             // fcw . C  per (cls,m)
__device__ float g_GD[NCLS];                     // fcw . b2 per cls

// ---------------- K1: setup — compose | hist | fold, all independent ----------------
__global__ void __launch_bounds__(256) setup_kernel(const int* __restrict__ p0,
                                                    const int* __restrict__ p1,
                                                    const int* __restrict__ p2,
                                                    const float* __restrict__ W0,
                                                    const float* __restrict__ b0,
                                                    const float* __restrict__ W1,
                                                    const float* __restrict__ b1,
                                                    const float* __restrict__ W2,
                                                    const float* __restrict__ b2,
                                                    const float* __restrict__ fcw,
                                                    const float* __restrict__ fcb,
                                                    float* __restrict__ out) {
    int t = threadIdx.x;
    int bx = blockIdx.x;

    if (bx < CB) {
        // ---- compose: m8[i] = p2[p1[p0[i]]], 4 per thread, MLP=4 ----
        int gid = bx * 256 + t;
        if (gid >= NGROUPS) return;
        int base = gid * 4;
        unsigned int pack;
        if (base + 3 < IN_FEATURES) {
            int4 a = ((const int4*)p0)[gid];
            int j0 = p1[a.x], j1 = p1[a.y], j2 = p1[a.z], j3 = p1[a.w];
            unsigned int m0 = p2[j0], m1 = p2[j1], m2 = p2[j2], m3 = p2[j3];
            pack = m0 | (m1 << 8) | (m2 << 16) | (m3 << 24);
        } else {
            pack = 0;
            for (int c = 0; c < 4; c++)
                if (base + c < IN_FEATURES)
                    pack |= ((unsigned int)p2[p1[p0[base + c]]]) << (8 * c);
        }
        g_m8[gid] = pack;
        return;
    }

    if (bx < CB + HB) {
        // ---- hist: cc1 over p2[p1[j]] (4 j's/thread), cnt2 over p2 ----
        __shared__ float s_cc1[NBINS], s_cnt2[NBINS];
        int h = bx - CB;
        if (t < NBINS) { s_cc1[t] = 0.f; s_cnt2[t] = 0.f; }
        __syncthreads();

        int g = h * 256 + t;                   // group of 4 j's, g < 16384
        int4 a = ((const int4*)p1)[g];
        atomicAdd(&s_cc1[p2[a.x]], 1.0f);
        atomicAdd(&s_cc1[p2[a.y]], 1.0f);
        atomicAdd(&s_cc1[p2[a.z]], 1.0f);
        atomicAdd(&s_cc1[p2[a.w]], 1.0f);

        if (h < 16) {                          // cnt2: 16 blocks x 256 x 4 = 16384
            int4 b = ((const int4*)p2)[g];
            atomicAdd(&s_cnt2[b.x], 1.0f);
            atomicAdd(&s_cnt2[b.y], 1.0f);
            atomicAdd(&s_cnt2[b.z], 1.0f);
            atomicAdd(&s_cnt2[b.w], 1.0f);
        }
        __syncthreads();
        if (t < NBINS) {
            g_pcc1[t * HB + h] = s_cc1[t];     // overwrite, no zero-init needed
            if (h < 16) g_pcnt2[t * 16 + h] = s_cnt2[t];
        }
        return;
    }

    // ---- fold: one block per class; redundant A/B/C compute; single-writer stores ----
    {
        __shared__ float u[64], v[64];
        __shared__ float sA[128], sB[128], sC[128];
        __shared__ float redG[256], redB[256], redC[256], redD[256];
        int cls = bx - CB - HB;

        if (t < 64) {
            float su = 0.f, sv = 0.f;
            #pragma unroll 8
            for (int c = 0; c < 32; c++) {
                float w = W1[t * 32 + c];
                su += w * W0[c];
                sv += w * b0[c];
            }
            u[t] = su; v[t] = sv;
        }
        __syncthreads();
        if (t < 128) {
            float sa = 0.f, sb = 0.f, sc = 0.f;
            #pragma unroll 8
            for (int c2 = 0; c2 < 64; c2++) {
                float w = W2[t * 64 + c2];
                sa += w * u[c2]; sb += w * v[c2]; sc += w * b1[c2];
            }
            sA[t] = sa; sB[t] = sb; sC[t] = sc;
        }
        __syncthreads();

        int m = t & 127;
        int half = t >> 7;                     // c3 in [half*64, half*64+64)
        float pG = 0.f, pB = 0.f, pC = 0.f, pD = 0.f;
        const float* fr = fcw + (size_t)cls * (128 * NBINS) + (size_t)(half * 64) * NBINS + m;
        #pragma unroll 16
        for (int i = 0; i < 64; i++) {
            float w = fr[i * NBINS];
            int c3 = half * 64 + i;
            pG += w * sA[c3];
            pB += w * sB[c3];
            pC += w * sC[c3];
            pD += w * b2[c3];
        }
        redG[t] = pG; redB[t] = pB; redC[t] = pC; redD[t] = pD;
        __syncthreads();
        if (t < 128) {
            g_Gt[m * NCLS + cls]  = redG[t] + redG[t + 128];   // transposed
            g_GB[cls * NBINS + m] = redB[t] + redB[t + 128];
            g_GC[cls * NBINS + m] = redC[t] + redC[t + 128];
        }
        if (t < 128) redD[t] += redD[t + 128];
        __syncthreads();
        #pragma unroll
        for (int s = 64; s > 0; s >>= 1) {
            if (t < s) redD[t] += redD[t + s];
            __syncthreads();
        }
        if (t == 0) g_GD[cls] = redD[0];
        if (t < BATCH) out[t * NCLS + cls] = fcb[cls];
        return;
    }
}

// ---------------- K2: accum + transposed-dot epilogue; block 864 = K(bias) block ----------------
__global__ void __launch_bounds__(ACC_THREADS) accum_kernel(const float* __restrict__ x,
                                                            float* __restrict__ out) {
    __shared__ float bins[NBINS * ACC_THREADS];  // 32 KB
    __shared__ float sm2[NBINS];
    int t = threadIdx.x;
    int bx = blockIdx.x;

    if (bx == ACC_BLOCKS) {
        // ---- K block: finalize cc1/cnt2 and add bias-propagation constants ----
        __shared__ float sK[NCLS];
        float cc1_0 = 0.f, cc1_1 = 0.f, cn2_0 = 0.f, cn2_1 = 0.f;
        {
            const float4* r0 = (const float4*)(g_pcc1 + t * HB);
            const float4* r1 = (const float4*)(g_pcc1 + (t + 64) * HB);
            #pragma unroll
            for (int i = 0; i < HB / 4; i++) {
                float4 a = r0[i], b = r1[i];
                cc1_0 += a.x + a.y + a.z + a.w;
                cc1_1 += b.x + b.y + b.z + b.w;
            }
            const float4* s0 = (const float4*)(g_pcnt2 + t * 16);
            const float4* s1 = (const float4*)(g_pcnt2 + (t + 64) * 16);
            #pragma unroll
            for (int i = 0; i < 4; i++) {
                float4 a = s0[i], b = s1[i];
                cn2_0 += a.x + a.y + a.z + a.w;
                cn2_1 += b.x + b.y + b.z + b.w;
            }
        }
        int lid = t & 31, wid = t >> 5;
        #pragma unroll
        for (int cls = 0; cls < NCLS; cls++) {
            float a = g_GB[cls * NBINS + t] * cc1_0 + g_GB[cls * NBINS + t + 64] * cc1_1
                    + g_GC[cls * NBINS + t] * cn2_0 + g_GC[cls * NBINS + t + 64] * cn2_1;
            #pragma unroll
            for (int off = 16; off > 0; off >>= 1)
                a += __shfl_xor_sync(0xFFFFFFFFu, a, off);
            if (lid == 0) bins[cls * 2 + wid] = a;      // reuse smem
        }
        __syncthreads();
        if (t < NCLS) sK[t] = bins[t * 2] + bins[t * 2 + 1] + g_GD[t];
        __syncthreads();
        for (int i = t; i < BATCH * NCLS; i += ACC_THREADS)
            atomicAdd(&out[i], sK[i % NCLS]);
        return;
    }

    // ---- accum block ----
    int c = bx % ACC_CHUNKS;
    int r = bx / ACC_CHUNKS;
    #pragma unroll
    for (int b = 0; b < NBINS; b++) bins[b * ACC_THREADS + t] = 0.f;

    const float* xr = x + (size_t)r * IN_FEATURES;
    int p = (4 - (r & 3)) & 3;                 // alignment phase (IN%4==1)
    int Kv = (IN_FEATURES - p) >> 2;
    int ck = (Kv + ACC_CHUNKS - 1) / ACC_CHUNKS;
    int k0 = c * ck;
    int k1 = min(k0 + ck, Kv);

    const unsigned int* mu = g_m8;
    const float4* xv = (const float4*)(xr + p);
    int sh = 8 * p;

    for (int k = k0 + t; k < k1; k += ACC_THREADS) {
        unsigned int u0 = mu[k], u1 = mu[k + 1];
        unsigned int b = __funnelshift_r(u0, u1, sh);
        float4 X = xv[k];
        bins[(int)(b & 255u)         * ACC_THREADS + t] += X.x;
        bins[(int)((b >> 8) & 255u)  * ACC_THREADS + t] += X.y;
        bins[(int)((b >> 16) & 255u) * ACC_THREADS + t] += X.z;
        bins[(int)(b >> 24)          * ACC_THREADS + t] += X.w;
    }

    const unsigned char* m8b = (const unsigned char*)g_m8;
    if (c == 0 && t < p) {
        bins[(int)m8b[t] * ACC_THREADS + t] += xr[t];
    }
    int tail0 = p + 4 * Kv;
    int ntail = IN_FEATURES - tail0;
    if (c == ACC_CHUNKS - 1 && t < ntail) {
        bins[(int)m8b[tail0 + t] * ACC_THREADS + t] += xr[tail0 + t];
    }
    __syncthreads();

    // reduce 64 private columns: thread t owns bins t and t+64
    float s0 = 0.f, s1 = 0.f;
    #pragma unroll 8
    for (int l = 0; l < ACC_THREADS; l++) {
        int lc = (l + t) & (ACC_THREADS - 1);
        s0 += bins[t * ACC_THREADS + lc];
        s1 += bins[(t + 64) * ACC_THREADS + lc];
    }
    sm2[t] = s0;
    sm2[t + 64] = s1;
    __syncthreads();

    // transposed dot: threads 0..39 -> (cls = t%20, half = t/20), 64 FMAs each,
    // coalesced loads from g_Gt[m][cls]; one atomicAdd per thread.
    if (t < 2 * NCLS) {
        int cls = t % NCLS;
        int half = t / NCLS;
        int mbase = half * 64;
        float a0 = 0.f, a1 = 0.f;
        const float* gt = g_Gt + (size_t)mbase * NCLS + cls;
        #pragma unroll 8
        for (int j = 0; j < 64; j += 2) {
            a0 += gt[j * NCLS]       * sm2[mbase + j];
            a1 += gt[(j + 1) * NCLS] * sm2[mbase + j + 1];
        }
        atomicAdd(&out[r * NCLS + cls], a0 + a1);
    }
}

// ---------------- launch ----------------
extern "C" void kernel_launch(void* const* d_in, const int* in_sizes, int n_in,
                              void* d_out, int out_size) {
    const float* x   = (const float*)d_in[0];
    const float* W0  = (const float*)d_in[1];
    const float* b0  = (const float*)d_in[2];
    const float* W1  = (const float*)d_in[3];
    const float* b1  = (const float*)d_in[4];
    const float* W2  = (const float*)d_in[5];
    const float* b2  = (const float*)d_in[6];
    const float* fcw = (const float*)d_in[7];
    const float* fcb = (const float*)d_in[8];
    const int*   p0  = (const int*)d_in[9];
    const int*   p1  = (const int*)d_in[10];
    const int*   p2  = (const int*)d_in[11];
    float* out = (float*)d_out;

    setup_kernel<<<SETUP_BLOCKS, 256>>>(p0, p1, p2, W0, b0, W1, b1, W2, b2, fcw, fcb, out);
    accum_kernel<<<ACC_BLOCKS + 1, ACC_THREADS>>>(x, out);
}